// round 17
// baseline (speedup 1.0000x reference)
#include <cuda_runtime.h>
#include <cuda_bf16.h>

// Problem constants
#define B_    64
#define C_    2048
#define HW_   576
#define HW4_  144          // HW_/4 float4 groups per channel row
#define NBLK  32           // k1 tiles per (t,b): 64 channels each
#define CPS   16           // channels per (block, csub)
#define NCLS  16           // NUM_CLASSES

// Scratch (allocation-free rule: __device__ globals; zero at module load).
// g_lum[par][t][b][p]: t=0 -> lum_v, t=1 -> lum_i. Parity ping-pong:
// k1(N) accumulates par, zeroes 1-par; k2(N) flips par at the very end.
// No other cross-launch state: k2 is a single block with no atomics.
__device__ float g_lum[2][2][B_][HW_];
__device__ int   g_parity;

// ---------------------------------------------------------------------------
// Kernel 1 (frozen stream): float4 loads, smem fold, 4 REDG.F32 atomicAdd
// into g_lum[par][t][b]. Zeroes other parity buffer (18 floats/block).
// grid = (NBLK, B, 2) = 4096 blocks, block = 576, 3 blocks/SM.
// ---------------------------------------------------------------------------
__global__ void __launch_bounds__(576, 3)
k_lum_partial(const float* __restrict__ fv, const float* __restrict__ fi) {
    const int blk  = blockIdx.x;
    const int b    = blockIdx.y;
    const int t    = blockIdx.z;
    const int tid  = threadIdx.x;
    const int q    = tid % HW4_;
    const int csub = tid / HW4_;

    const int par = g_parity;

    // Zero the other parity buffer: 73728 floats / 4096 blocks = 18 each.
    {
        const int blin = blk + NBLK * (b + B_ * t);    // 0..4095
        if (tid < 18) ((float*)g_lum[1 - par])[blin * 18 + tid] = 0.0f;
    }

    const float* __restrict__ f = t ? fi : fv;
    const float4* __restrict__ base = (const float4*)
        (f + ((size_t)b * C_ + (size_t)blk * 64) * HW_)
        + (size_t)csub * CPS * HW4_ + q;

    float ax = 0.f, ay = 0.f, az = 0.f, aw = 0.f;
#pragma unroll 8
    for (int it = 0; it < CPS; ++it) {
        float4 x = base[(size_t)it * HW4_];
        ax = fmaf(x.x, x.x, ax);
        ay = fmaf(x.y, x.y, ay);
        az = fmaf(x.z, x.z, az);
        aw = fmaf(x.w, x.w, aw);
    }

    __shared__ float4 sh[4][HW4_];
    sh[csub][q] = make_float4(ax, ay, az, aw);
    __syncthreads();

    if (csub == 0) {
        float4 a = sh[0][q], c1 = sh[1][q], c2 = sh[2][q], c3 = sh[3][q];
        a.x += c1.x + c2.x + c3.x;
        a.y += c1.y + c2.y + c3.y;
        a.z += c1.z + c2.z + c3.z;
        a.w += c1.w + c2.w + c3.w;
        float* dst = &g_lum[par][t][b][4 * q];
        atomicAdd(dst + 0, a.x);
        atomicAdd(dst + 1, a.y);
        atomicAdd(dst + 2, a.z);
        atomicAdd(dst + 3, a.w);
    }
}

// ---------------------------------------------------------------------------
// Kernel 2: SINGLE-BLOCK class-factored finish. grid = 1, block = 576.
// Thread p owns column p:
//   pass 1: acc += sum_jj (n_jj-1)*(lv^2+li^2) + 2*lv*li  (fp32 terms,
//           double accumulator; per-term magnitude ~3e7, rounding ~4e-6 rel)
//   pass 2: rows in class-sorted order -> acc -= 2 * U_c[p] * W_c[p]
// Reduce 576 doubles, thread 0 writes loss and flips parity. No atomics,
// no tickets, no cross-block state. Labels are int32 (JAX x64 disabled).
// ---------------------------------------------------------------------------
__global__ void __launch_bounds__(576, 1)
k_finish(const int* __restrict__ labels, float* __restrict__ out) {
    const int tid  = threadIdx.x;   // column p
    const int lane = tid & 31;
    const int wid  = tid >> 5;      // 0..17

    __shared__ int    s_lab[B_];
    __shared__ int    s_cnt[NCLS];
    __shared__ int    s_ord[B_];    // rows sorted by class
    __shared__ int    s_npairs;
    __shared__ double s_red[18];

    if (tid < B_) s_lab[tid] = labels[tid];
    __syncthreads();

    if (tid == 0) {
        int cnt[NCLS];
        for (int c = 0; c < NCLS; ++c) cnt[c] = 0;
        for (int jj = 0; jj < B_; ++jj) cnt[s_lab[jj]]++;
        int np = 0, start[NCLS], pos = 0;
        for (int c = 0; c < NCLS; ++c) {
            np += cnt[c] * (cnt[c] - 1);
            start[c] = pos; pos += cnt[c];
            s_cnt[c] = cnt[c];
        }
        s_npairs = np;
        for (int jj = 0; jj < B_; ++jj) s_ord[start[s_lab[jj]]++] = jj;
    }
    __syncthreads();

    const int par = g_parity;
    const float* __restrict__ LV = &g_lum[par][0][0][0];
    const float* __restrict__ LI = &g_lum[par][1][0][0];

    double acc = 0.0;

    // pass 1: weighted per-row terms (coalesced: warp reads 32 consec cols)
#pragma unroll 4
    for (int jj = 0; jj < B_; ++jj) {
        const float lv = LV[jj * HW_ + tid];
        const float li = LI[jj * HW_ + tid];
        const float w  = (float)(s_cnt[s_lab[jj]] - 1);
        const float term = fmaf(w, fmaf(lv, lv, li * li), 2.0f * lv * li);
        acc += (double)term;
    }

    // pass 2: class dots in class-sorted order (rows L1/L2-hot from pass 1)
    {
        int idx = 0;
        for (int c = 0; c < NCLS; ++c) {
            float u = 0.f, w2 = 0.f;
            const int n = s_cnt[c];
            for (int k = 0; k < n; ++k) {
                const int jj = s_ord[idx++];
                u  += LV[jj * HW_ + tid];
                w2 += LI[jj * HW_ + tid];
            }
            acc -= 2.0 * (double)u * (double)w2;
        }
    }

    // reduce 576 doubles
#pragma unroll
    for (int off = 16; off > 0; off >>= 1)
        acc += __shfl_down_sync(0xffffffffu, acc, off);
    if (lane == 0) s_red[wid] = acc;
    __syncthreads();

    if (tid == 0) {
        double total = 0.0;
#pragma unroll
        for (int k = 0; k < 18; ++k) total += s_red[k];
        const int np = s_npairs;
        out[0] = (np > 0)
               ? (float)(total / (double)HW_ / (double)np) : 0.0f;
        g_parity = par ^ 1;              // flip for next replay
        __threadfence();
    }
}

extern "C" void kernel_launch(void* const* d_in, const int* in_sizes, int n_in,
                              void* d_out, int out_size) {
    const float* fv     = (const float*)d_in[0];
    const float* fi     = (const float*)d_in[1];
    const int*   labels = (const int*)d_in[2];
    float*       out    = (float*)d_out;

    k_lum_partial<<<dim3(NBLK, B_, 2), 576>>>(fv, fi);
    k_finish<<<1, 576>>>(labels, out);
}